// round 3
// baseline (speedup 1.0000x reference)
#include <cuda_runtime.h>
#include <cstdint>

// ============================================================================
// BCQLinear: y = (x[:, in_reorder] @ dequant(qweight))[:, out_reorder]
// M=128, K=N=4096, WBITS=3, GS=OFI=128.
// compute_100-safe: mma.sync m16n8k8 tf32 (RNA), register-fused 3-bit dequant.
// R3: 512-thread CTAs (4 warps/SMSP), kh-split (KSPLIT_EFF=8), fast dequant
//     (no I2F), vectorized prep, inverse-permutation finalize.
// ============================================================================

#define M_TOK   128
#define IN_F    4096
#define OUT_F   4096
#define NGRP    32
#define NSPLIT  4            // grid.y
#define NPLANE  8            // effective K-splits (2 per CTA)

// Scratch (static __device__ — no allocations)
__device__ float g_x_frag[NGRP * 16 * 8 * 32 * 4];       // 2 MB  A fragments
__device__ float g_t_part[NPLANE * M_TOK * OUT_F];       // 16 MB K-split partials
__device__ int   g_inv_out[OUT_F];

__device__ __forceinline__ uint32_t f2tf32(float f) {
    uint32_t u;
    asm("cvt.rna.tf32.f32 %0, %1;" : "=r"(u) : "f"(f));   // RNA: zero-mean error
    return u;
}

// ---------------------------------------------------------------------------
// Kernel 1: gather x[:, in_reorder], tf32-round, A-fragment layout.
// 4 gathers per thread (MLP), one float4 coalesced store.
// frag map (m16n8k8.tf32 A): r0:(row,k) r1:(row+8,k) r2:(row,k+4) r3:(row+8,k+4)
// ---------------------------------------------------------------------------
__global__ __launch_bounds__(256)
void prep_x_kernel(const float* __restrict__ x, const int* __restrict__ in_reorder) {
    const int t    = blockIdx.x * 256 + threadIdx.x;     // 131072 threads
    const int lane = t & 31;
    const int mt   = (t >> 5) & 7;
    const int ks   = (t >> 8) & 15;
    const int g    = (t >> 12) & 31;
    const int row  = lane >> 2, kc = lane & 3;
    const int mb   = mt * 16, kb = g * 128 + ks * 8;
    float4 v;
    v.x = x[(mb + row    ) * IN_F + __ldg(&in_reorder[kb + kc    ])];
    v.y = x[(mb + row + 8) * IN_F + __ldg(&in_reorder[kb + kc    ])];
    v.z = x[(mb + row    ) * IN_F + __ldg(&in_reorder[kb + kc + 4])];
    v.w = x[(mb + row + 8) * IN_F + __ldg(&in_reorder[kb + kc + 4])];
    v.x = __uint_as_float(f2tf32(v.x));
    v.y = __uint_as_float(f2tf32(v.y));
    v.z = __uint_as_float(f2tf32(v.z));
    v.w = __uint_as_float(f2tf32(v.w));
    ((float4*)g_x_frag)[t] = v;
}

__global__ __launch_bounds__(256)
void inv_kernel(const int* __restrict__ out_reorder) {
    const int c = blockIdx.x * 256 + threadIdx.x;        // 4096
    g_inv_out[__ldg(&out_reorder[c])] = c;
}

// ---------------------------------------------------------------------------
// Kernel 2: fused 3-bit dequant + tf32 mma.sync GEMM.
// grid (32 out-blocks, 4 splits) = 128 CTAs, 512 threads (16 warps).
// wid = kh*8 + nq*2 + mh : kh = k-half (4 groups), nq = n-quarter, mh = m-half.
// ---------------------------------------------------------------------------
__global__ __launch_bounds__(512, 1)
void bcq_gemm_kernel(const int* __restrict__ qweight,
                     const float* __restrict__ alpha,
                     const float* __restrict__ beta,
                     const int* __restrict__ offset)
{
    __shared__ int Qsm[2 * 1536];             // one (group, out-block) per k-half
    const int tid  = threadIdx.x;
    const int lane = tid & 31;
    const int wid  = tid >> 5;
    const int nb = blockIdx.x, split = blockIdx.y;
    const int kh = wid >> 3;                  // k-half (0..1)
    const int mh = wid & 1;                   // m-half (0..1)
    const int nq = (wid >> 1) & 3;            // n-quarter == qweight word sub-index j
    const int htid = tid & 255;               // thread id within k-half
    int* Qh = Qsm + kh * 1536;

    float acc[4][4][4];
    #pragma unroll
    for (int a = 0; a < 4; a++)
        #pragma unroll
        for (int b = 0; b < 4; b++)
            #pragma unroll
            for (int c = 0; c < 4; c++) acc[a][b][c] = 0.f;

    // --- prefetch group 0 of this k-half ---
    int   qn[6];
    float c1n[4], c0n[4];
    {
        const int g0 = split * 8 + kh * 4;
        const int* src = qweight + __ldg(&offset[g0 * 32 + nb]);
        #pragma unroll
        for (int u = 0; u < 6; u++) qn[u] = __ldg(src + htid + u * 256);
        #pragma unroll
        for (int nt = 0; nt < 4; nt++) {
            const int o = nq * 32 + nt * 8 + (lane >> 2);
            const float a = __ldg(&alpha[g0 * OUT_F + nb * 128 + o]);
            const float b = __ldg(&beta [g0 * OUT_F + nb * 128 + o]);
            c1n[nt] = 2.f * a;                 // w = v*(2a) + (b - 7a),  q = 2v-7
            c0n[nt] = fmaf(-7.f, a, b);
        }
    }

    for (int gi = 0; gi < 4; gi++) {
        const int g = split * 8 + kh * 4 + gi;

        float c1[4], c0[4];
        #pragma unroll
        for (int nt = 0; nt < 4; nt++) { c1[nt] = c1n[nt]; c0[nt] = c0n[nt]; }

        __syncthreads();                       // Qsm free from previous group
        #pragma unroll
        for (int u = 0; u < 6; u++) Qh[htid + u * 256] = qn[u];
        __syncthreads();                       // Qsm visible

        if (gi + 1 < 4) {                      // prefetch next group
            const int gnx = g + 1;
            const int* src = qweight + __ldg(&offset[gnx * 32 + nb]);
            #pragma unroll
            for (int u = 0; u < 6; u++) qn[u] = __ldg(src + htid + u * 256);
            #pragma unroll
            for (int nt = 0; nt < 4; nt++) {
                const int o = nq * 32 + nt * 8 + (lane >> 2);
                const float a = __ldg(&alpha[gnx * OUT_F + nb * 128 + o]);
                const float b = __ldg(&beta [gnx * OUT_F + nb * 128 + o]);
                c1n[nt] = 2.f * a;
                c0n[nt] = fmaf(-7.f, a, b);
            }
        }

        const float4* Abase =
            ((const float4*)g_x_frag) + (size_t)g * (16 * 8 * 32) + lane;

        #pragma unroll 4
        for (int ks = 0; ks < 16; ks++) {
            // --- A fragments: 4 coalesced LDG.128 (L2-resident) ---
            uint32_t A[4][4];
            #pragma unroll
            for (int mt = 0; mt < 4; mt++) {
                const float4 t = __ldg((const float4*)&Abase[(ks * 8 + mh * 4 + mt) * 32]);
                A[mt][0] = __float_as_uint(t.x);
                A[mt][1] = __float_as_uint(t.y);
                A[mt][2] = __float_as_uint(t.z);
                A[mt][3] = __float_as_uint(t.w);
            }

            // --- qweight words (6 LDS, broadcast within lane-quads) ---
            const int i0 = ks * 8 + (lane & 3);
            const uint32_t q0l = (uint32_t)Qh[       i0      * 4 + nq];
            const uint32_t q0h = (uint32_t)Qh[      (i0 + 4) * 4 + nq];
            const uint32_t q1l = (uint32_t)Qh[512  + i0      * 4 + nq];
            const uint32_t q1h = (uint32_t)Qh[512  + (i0 + 4) * 4 + nq];
            const uint32_t q2l = (uint32_t)Qh[1024 + i0      * 4 + nq];
            const uint32_t q2h = (uint32_t)Qh[1024 + (i0 + 4) * 4 + nq];

            // --- dequant into B fragments (no I2F: exponent-bias trick) ---
            uint32_t B[4][2];
            #pragma unroll
            for (int nt = 0; nt < 4; nt++) {
                const int sh = nt * 8 + (lane >> 2);
                const uint32_t vl = ((q0l >> sh) & 1u)
                                  | (((q1l >> sh) & 1u) << 1)
                                  | (((q2l >> sh) & 1u) << 2);
                const uint32_t vh = ((q0h >> sh) & 1u)
                                  | (((q1h >> sh) & 1u) << 1)
                                  | (((q2h >> sh) & 1u) << 2);
                const float fl = __uint_as_float(0x4B000000u | vl) - 8388608.f;
                const float fh = __uint_as_float(0x4B000000u | vh) - 8388608.f;
                B[nt][0] = f2tf32(fmaf(fl, c1[nt], c0[nt]));
                B[nt][1] = f2tf32(fmaf(fh, c1[nt], c0[nt]));
            }

            // --- 16 mma.sync per warp per k-step ---
            #pragma unroll
            for (int mt = 0; mt < 4; mt++)
                #pragma unroll
                for (int nt = 0; nt < 4; nt++)
                    asm volatile(
                        "mma.sync.aligned.m16n8k8.row.col.f32.tf32.tf32.f32 "
                        "{%0,%1,%2,%3}, {%4,%5,%6,%7}, {%8,%9}, {%0,%1,%2,%3};"
                        : "+f"(acc[mt][nt][0]), "+f"(acc[mt][nt][1]),
                          "+f"(acc[mt][nt][2]), "+f"(acc[mt][nt][3])
                        : "r"(A[mt][0]), "r"(A[mt][1]), "r"(A[mt][2]), "r"(A[mt][3]),
                          "r"(B[nt][0]), "r"(B[nt][1]));
        }
    }

    // --- epilogue: K-split partials, plane = split*2 + kh (deterministic) ---
    float* dst = g_t_part + (size_t)(split * 2 + kh) * (M_TOK * OUT_F);
    #pragma unroll
    for (int mt = 0; mt < 4; mt++) {
        const int row0 = mh * 64 + mt * 16 + (lane >> 2);
        #pragma unroll
        for (int nt = 0; nt < 4; nt++) {
            const int col = nb * 128 + nq * 32 + nt * 8 + (lane & 3) * 2;
            *(float2*)&dst[ row0      * OUT_F + col] =
                make_float2(acc[mt][nt][0], acc[mt][nt][1]);
            *(float2*)&dst[(row0 + 8) * OUT_F + col] =
                make_float2(acc[mt][nt][2], acc[mt][nt][3]);
        }
    }
}

// ---------------------------------------------------------------------------
// Kernel 3: reduce 8 K-splits (coalesced reads) + scatter via inverse perm
// ---------------------------------------------------------------------------
__global__ __launch_bounds__(256)
void finalize_kernel(float* __restrict__ y) {
    const int idx = blockIdx.x * 256 + threadIdx.x;      // 524288 = m*4096+n
    const size_t S = (size_t)M_TOK * OUT_F;
    float s = 0.f;
    #pragma unroll
    for (int p = 0; p < NPLANE; p++) s += g_t_part[p * S + idx];
    const int m = idx >> 12, n = idx & (OUT_F - 1);
    y[(size_t)m * OUT_F + g_inv_out[n]] = s;             // scattered 4B write
}

// ---------------------------------------------------------------------------
// Launch
// ---------------------------------------------------------------------------
extern "C" void kernel_launch(void* const* d_in, const int* in_sizes, int n_in,
                              void* d_out, int out_size) {
    const float* x           = (const float*)d_in[0];
    const int*   qweight     = (const int*)  d_in[1];
    const float* alpha       = (const float*)d_in[2];
    const float* beta        = (const float*)d_in[3];
    // d_in[4] = block_bitwidth (uniform 3, unused)
    const int*   offset      = (const int*)  d_in[5];
    const int*   in_reorder  = (const int*)  d_in[6];
    const int*   out_reorder = (const int*)  d_in[7];
    float* y = (float*)d_out;

    prep_x_kernel<<<512, 256>>>(x, in_reorder);
    inv_kernel<<<16, 256>>>(out_reorder);
    bcq_gemm_kernel<<<dim3(32, NSPLIT), 512>>>(qweight, alpha, beta, offset);
    finalize_kernel<<<2048, 256>>>(y);
}

// round 5
// speedup vs baseline: 1.5529x; 1.5529x over previous
#include <cuda_runtime.h>
#include <cstdint>

// ============================================================================
// BCQLinear: y = (x[:, in_reorder] @ dequant(qweight))[:, out_reorder]
// M=128, K=N=4096, WBITS=3, GS=OFI=128.
// compute_100-safe: mma.sync m16n8k8 tf32 (RNA), register-fused 3-bit dequant.
// R5: R4 with corrected cp.async plane strides (smem +2048B, gmem +512 ints).
//     grid (32,8)=256 CTAs @ 256 thr, 2 CTA/SM, double-buffered qweight,
//     two-pass coalesced finalize.
// ============================================================================

#define M_TOK   128
#define IN_F    4096
#define OUT_F   4096
#define NGRP    32
#define NSPLIT  8            // grid.y; 4 groups per CTA
#define NPLANE  8

// Scratch (static __device__ — no allocations)
__device__ float g_x_frag[NGRP * 16 * 8 * 32 * 4];       // 2 MB  A fragments
__device__ float g_t_part[NPLANE * M_TOK * OUT_F];       // 16 MB K-split partials
__device__ float g_t_sum[M_TOK * OUT_F];                 // 2 MB  reduced sum

__device__ __forceinline__ uint32_t f2tf32(float f) {
    uint32_t u;
    asm("cvt.rna.tf32.f32 %0, %1;" : "=r"(u) : "f"(f));   // RNA: zero-mean error
    return u;
}
__device__ __forceinline__ uint32_t smem_u32(const void* p) {
    uint32_t a;
    asm("{ .reg .u64 t; cvta.to.shared.u64 t, %1; cvt.u32.u64 %0, t; }"
        : "=r"(a) : "l"(p));
    return a;
}
__device__ __forceinline__ void cp_async8(uint32_t saddr, const void* gptr) {
    asm volatile("cp.async.ca.shared.global [%0], [%1], 8;"
                 :: "r"(saddr), "l"(gptr));
}
#define CP_COMMIT() asm volatile("cp.async.commit_group;" ::: "memory")
#define CP_WAIT0()  asm volatile("cp.async.wait_group 0;" ::: "memory")

// ---------------------------------------------------------------------------
// Kernel 1: gather x[:, in_reorder], tf32-round, A-fragment layout.
// frag map (m16n8k8.tf32 A): r0:(row,k) r1:(row+8,k) r2:(row,k+4) r3:(row+8,k+4)
// ---------------------------------------------------------------------------
__global__ __launch_bounds__(256)
void prep_x_kernel(const float* __restrict__ x, const int* __restrict__ in_reorder) {
    const int t    = blockIdx.x * 256 + threadIdx.x;     // 131072 threads
    const int lane = t & 31;
    const int mt   = (t >> 5) & 7;
    const int ks   = (t >> 8) & 15;
    const int g    = (t >> 12) & 31;
    const int row  = lane >> 2, kc = lane & 3;
    const int mb   = mt * 16, kb = g * 128 + ks * 8;
    float4 v;
    v.x = x[(mb + row    ) * IN_F + __ldg(&in_reorder[kb + kc    ])];
    v.y = x[(mb + row + 8) * IN_F + __ldg(&in_reorder[kb + kc    ])];
    v.z = x[(mb + row    ) * IN_F + __ldg(&in_reorder[kb + kc + 4])];
    v.w = x[(mb + row + 8) * IN_F + __ldg(&in_reorder[kb + kc + 4])];
    v.x = __uint_as_float(f2tf32(v.x));
    v.y = __uint_as_float(f2tf32(v.y));
    v.z = __uint_as_float(f2tf32(v.z));
    v.w = __uint_as_float(f2tf32(v.w));
    ((float4*)g_x_frag)[t] = v;
}

// ---------------------------------------------------------------------------
// Kernel 2: fused 3-bit dequant + tf32 mma.sync GEMM.
// grid (32 out-blocks, 8 K-splits) = 256 CTAs, 256 threads, 2 CTAs/SM.
// warp: mh = wid&1 (m-half), nq = wid>>1 (n-quarter == qweight word index j).
// Qsm buffer layout: [buf][plane 3][i 512] ints; per-buffer 6144 B.
// Per-thread cp.async: 8 B at plane offsets 0 / 2048 / 4096 B
//                      from gmem offsets tid*2 / +512 / +1024 ints.
// ---------------------------------------------------------------------------
__global__ __launch_bounds__(256, 2)
void bcq_gemm_kernel(const int* __restrict__ qweight,
                     const float* __restrict__ alpha,
                     const float* __restrict__ beta,
                     const int* __restrict__ offset)
{
    __shared__ int Qsm[2 * 1536];             // double-buffered (group, out-block)
    const int tid  = threadIdx.x;
    const int lane = tid & 31;
    const int wid  = tid >> 5;
    const int nb = blockIdx.x, split = blockIdx.y;
    const int mh = wid & 1;
    const int nq = wid >> 1;
    const uint32_t qsm_base = smem_u32(Qsm) + tid * 8;

    float acc[4][4][4];
    #pragma unroll
    for (int a = 0; a < 4; a++)
        #pragma unroll
        for (int b = 0; b < 4; b++)
            #pragma unroll
            for (int c = 0; c < 4; c++) acc[a][b][c] = 0.f;

    // prologue: async-copy group 0's qweight block into buffer 0
    {
        const int* src = qweight + __ldg(&offset[(split * 4) * 32 + nb]) + tid * 2;
        cp_async8(qsm_base,        src);
        cp_async8(qsm_base + 2048, src + 512);
        cp_async8(qsm_base + 4096, src + 1024);
        CP_COMMIT();
    }

    for (int gi = 0; gi < 4; gi++) {
        const int g = split * 4 + gi;

        // issue alpha/beta LDGs first so their latency overlaps the cp wait
        float c1[4], c0[4];
        #pragma unroll
        for (int nt = 0; nt < 4; nt++) {
            const int o = nq * 32 + nt * 8 + (lane >> 2);
            const float a = __ldg(&alpha[g * OUT_F + nb * 128 + o]);
            const float b = __ldg(&beta [g * OUT_F + nb * 128 + o]);
            c1[nt] = 2.f * a;                  // w = v*(2a) + (b-7a), q = 2v-7
            c0[nt] = fmaf(-7.f, a, b);
        }

        CP_WAIT0();
        __syncthreads();                       // buf[gi&1] ready; buf[(gi+1)&1] free

        if (gi < 3) {                          // async prefetch next group
            const int* src = qweight + __ldg(&offset[(g + 1) * 32 + nb]) + tid * 2;
            const uint32_t nb_ = qsm_base + ((gi + 1) & 1) * 6144;
            cp_async8(nb_,        src);
            cp_async8(nb_ + 2048, src + 512);
            cp_async8(nb_ + 4096, src + 1024);
            CP_COMMIT();
        }

        const int* Qh = Qsm + (gi & 1) * 1536;
        const float4* Abase =
            ((const float4*)g_x_frag) + (size_t)g * (16 * 8 * 32) + lane;

        #pragma unroll 4
        for (int ks = 0; ks < 16; ks++) {
            // --- A fragments: 4 coalesced LDG.128 (L2-resident) ---
            uint32_t A[4][4];
            #pragma unroll
            for (int mt = 0; mt < 4; mt++) {
                const float4 t = __ldg((const float4*)&Abase[(ks * 8 + mh * 4 + mt) * 32]);
                A[mt][0] = __float_as_uint(t.x);
                A[mt][1] = __float_as_uint(t.y);
                A[mt][2] = __float_as_uint(t.z);
                A[mt][3] = __float_as_uint(t.w);
            }

            // --- qweight words (6 LDS, broadcast within lane-quads) ---
            const int i0 = ks * 8 + (lane & 3);
            const uint32_t q0l = (uint32_t)Qh[       i0      * 4 + nq];
            const uint32_t q0h = (uint32_t)Qh[      (i0 + 4) * 4 + nq];
            const uint32_t q1l = (uint32_t)Qh[512  + i0      * 4 + nq];
            const uint32_t q1h = (uint32_t)Qh[512  + (i0 + 4) * 4 + nq];
            const uint32_t q2l = (uint32_t)Qh[1024 + i0      * 4 + nq];
            const uint32_t q2h = (uint32_t)Qh[1024 + (i0 + 4) * 4 + nq];

            // --- dequant into B fragments (exponent-bias trick, no I2F) ---
            uint32_t B[4][2];
            #pragma unroll
            for (int nt = 0; nt < 4; nt++) {
                const int sh = nt * 8 + (lane >> 2);
                const uint32_t vl = ((q0l >> sh) & 1u)
                                  | (((q1l >> sh) & 1u) << 1)
                                  | (((q2l >> sh) & 1u) << 2);
                const uint32_t vh = ((q0h >> sh) & 1u)
                                  | (((q1h >> sh) & 1u) << 1)
                                  | (((q2h >> sh) & 1u) << 2);
                const float fl = __uint_as_float(0x4B000000u | vl) - 8388608.f;
                const float fh = __uint_as_float(0x4B000000u | vh) - 8388608.f;
                B[nt][0] = f2tf32(fmaf(fl, c1[nt], c0[nt]));
                B[nt][1] = f2tf32(fmaf(fh, c1[nt], c0[nt]));
            }

            // --- 16 mma.sync per warp per k-step ---
            #pragma unroll
            for (int mt = 0; mt < 4; mt++)
                #pragma unroll
                for (int nt = 0; nt < 4; nt++)
                    asm volatile(
                        "mma.sync.aligned.m16n8k8.row.col.f32.tf32.tf32.f32 "
                        "{%0,%1,%2,%3}, {%4,%5,%6,%7}, {%8,%9}, {%0,%1,%2,%3};"
                        : "+f"(acc[mt][nt][0]), "+f"(acc[mt][nt][1]),
                          "+f"(acc[mt][nt][2]), "+f"(acc[mt][nt][3])
                        : "r"(A[mt][0]), "r"(A[mt][1]), "r"(A[mt][2]), "r"(A[mt][3]),
                          "r"(B[nt][0]), "r"(B[nt][1]));
        }
    }

    // --- epilogue: K-split partials, plane = split (deterministic) ---
    float* dst = g_t_part + (size_t)split * (M_TOK * OUT_F);
    #pragma unroll
    for (int mt = 0; mt < 4; mt++) {
        const int row0 = mh * 64 + mt * 16 + (lane >> 2);
        #pragma unroll
        for (int nt = 0; nt < 4; nt++) {
            const int col = nb * 128 + nq * 32 + nt * 8 + (lane & 3) * 2;
            *(float2*)&dst[ row0      * OUT_F + col] =
                make_float2(acc[mt][nt][0], acc[mt][nt][1]);
            *(float2*)&dst[(row0 + 8) * OUT_F + col] =
                make_float2(acc[mt][nt][2], acc[mt][nt][3]);
        }
    }
}

// ---------------------------------------------------------------------------
// Kernel 3a: reduce 8 planes, fully coalesced float4
// ---------------------------------------------------------------------------
__global__ __launch_bounds__(256)
void reduce_kernel() {
    const int i = blockIdx.x * 256 + threadIdx.x;        // 131072 float4s
    const float4* p = (const float4*)g_t_part;
    float4 s = p[i];
    #pragma unroll
    for (int pl = 1; pl < NPLANE; pl++) {
        const float4 t = p[pl * 131072 + i];
        s.x += t.x; s.y += t.y; s.z += t.z; s.w += t.w;
    }
    ((float4*)g_t_sum)[i] = s;
}

// ---------------------------------------------------------------------------
// Kernel 3b: output permutation — coalesced write, 4B gather read
// ---------------------------------------------------------------------------
__global__ __launch_bounds__(256)
void permute_kernel(const int* __restrict__ out_reorder, float* __restrict__ y) {
    const int idx = blockIdx.x * 256 + threadIdx.x;      // 524288 = m*4096+c
    const int m = idx >> 12, c = idx & (OUT_F - 1);
    y[idx] = g_t_sum[(m << 12) | __ldg(&out_reorder[c])];
}

// ---------------------------------------------------------------------------
// Launch
// ---------------------------------------------------------------------------
extern "C" void kernel_launch(void* const* d_in, const int* in_sizes, int n_in,
                              void* d_out, int out_size) {
    const float* x           = (const float*)d_in[0];
    const int*   qweight     = (const int*)  d_in[1];
    const float* alpha       = (const float*)d_in[2];
    const float* beta        = (const float*)d_in[3];
    // d_in[4] = block_bitwidth (uniform 3, unused)
    const int*   offset      = (const int*)  d_in[5];
    const int*   in_reorder  = (const int*)  d_in[6];
    const int*   out_reorder = (const int*)  d_in[7];
    float* y = (float*)d_out;

    prep_x_kernel<<<512, 256>>>(x, in_reorder);
    bcq_gemm_kernel<<<dim3(32, NSPLIT), 256>>>(qweight, alpha, beta, offset);
    reduce_kernel<<<512, 256>>>();
    permute_kernel<<<2048, 256>>>(out_reorder, y);
}